// round 13
// baseline (speedup 1.0000x reference)
#include <cuda_runtime.h>
#include <cstdint>

// FPS: B=8, N=65536, select 1024. 8-CTA cluster per batch.
// Tag-poll DSMEM exchange (round-10 proven) + per-slot speculative coord
// prefetch in the poll loop; pivot distributed via STS/LDS (winner-only wait).
// Reducer warp = highest wid (arbiter priority).

#define FPS_B  8
#define FPS_N  65536
#define FPS_NP 1024
#define FPS_CL 8
#define FPS_T  1024
#define NW     (FPS_T / 32)
#define NF4    2              // float4 loads per plane per thread
#define NPAIR  4              // f32x2 pairs per thread (8 points)

__device__ __forceinline__ uint64_t pack2(float a, float b) {
    uint64_t r; asm("mov.b64 %0, {%1, %2};" : "=l"(r) : "f"(a), "f"(b)); return r;
}
__device__ __forceinline__ void unpack2(uint64_t v, float& a, float& b) {
    asm("mov.b64 {%0, %1}, %2;" : "=f"(a), "=f"(b) : "l"(v));
}
__device__ __forceinline__ uint64_t add2(uint64_t a, uint64_t b) {
    uint64_t r; asm("add.rn.f32x2 %0, %1, %2;" : "=l"(r) : "l"(a), "l"(b)); return r;
}
__device__ __forceinline__ uint64_t mul2(uint64_t a, uint64_t b) {
    uint64_t r; asm("mul.rn.f32x2 %0, %1, %2;" : "=l"(r) : "l"(a), "l"(b)); return r;
}
__device__ __forceinline__ uint32_t ctarank() {
    uint32_t r; asm("mov.u32 %0, %%cluster_ctarank;" : "=r"(r)); return r;
}
__device__ __forceinline__ uint32_t smem_u32(const void* p) {
    uint32_t a;
    asm("{ .reg .u64 t; cvta.to.shared.u64 t, %1; cvt.u32.u64 %0, t; }" : "=r"(a) : "l"(p));
    return a;
}
__device__ __forceinline__ uint32_t redux_max_u32(uint32_t v) {
    uint32_t r; asm("redux.sync.max.u32 %0, %1, 0xFFFFFFFF;" : "=r"(r) : "r"(v)); return r;
}
__device__ __forceinline__ uint32_t mapa32(uint32_t laddr, uint32_t rank) {
    uint32_t r;
    asm("mapa.shared::cluster.u32 %0, %1, %2;" : "=r"(r) : "r"(laddr), "r"(rank));
    return r;
}
__device__ __forceinline__ void st_cluster_u64(uint32_t raddr, uint64_t v) {
    asm volatile("st.shared::cluster.u64 [%0], %1;" :: "r"(raddr), "l"(v) : "memory");
}
__device__ __forceinline__ uint64_t lds_volatile_u64(uint32_t addr) {
    uint64_t v;
    asm volatile("ld.volatile.shared.u64 %0, [%1];" : "=l"(v) : "r"(addr) : "memory");
    return v;
}

__global__ void __launch_bounds__(FPS_T, 1) __cluster_dims__(FPS_CL, 1, 1)
fps_kernel(const float* __restrict__ pts, float* __restrict__ out) {
    const int b      = blockIdx.x / FPS_CL;
    const uint32_t k = ctarank();
    const int tid    = threadIdx.x;
    const int lane   = tid & 31;
    const int wid    = tid >> 5;

    const float* __restrict__ xb = pts + (size_t)b * 3 * FPS_N;
    const float4* __restrict__ x4 = (const float4*)(xb);
    const float4* __restrict__ y4 = (const float4*)(xb + FPS_N);
    const float4* __restrict__ z4 = (const float4*)(xb + 2 * FPS_N);

    uint64_t xp[NPAIR], yp[NPAIR], zp[NPAIR];
    float dist[2 * NPAIR];
    int pbase[NF4];

    // CONSECUTIVE layout: thread t owns points [8t, 8t+8) of its CTA block
    // => lane/warp/slot order == index order (ballot+ffs tie-breaks valid).
#pragma unroll
    for (int j = 0; j < NF4; j++) {
        int f = (int)k * (FPS_N / 4 / FPS_CL) + 2 * tid + j;
        pbase[j] = 4 * f;
        float4 vx = x4[f], vy = y4[f], vz = z4[f];
        xp[2*j+0] = pack2(vx.x, vx.y);  xp[2*j+1] = pack2(vx.z, vx.w);
        yp[2*j+0] = pack2(vy.x, vy.y);  yp[2*j+1] = pack2(vy.z, vy.w);
        zp[2*j+0] = pack2(vz.x, vz.y);  zp[2*j+1] = pack2(vz.z, vz.w);
    }
#pragma unroll
    for (int p = 0; p < 2 * NPAIR; p++) dist[p] = 1e10f;

    __shared__ uint64_t s_wkey[NW];                             // (d<<32)|idx per warp
    __shared__ alignas(16) unsigned long long s_key[2][FPS_CL]; // msg: hi=d, lo=(tag<<24)|idx
    __shared__ alignas(16) float4 s_piv[NW];                    // per-warp pivot broadcast
    __shared__ uint32_t s_hist[FPS_NP];

    const uint32_t pair0 = smem_u32(&s_key[0][0]);
    const uint32_t pair1 = smem_u32(&s_key[1][0]);

    uint32_t r_slot0 = 0, r_slot1 = 0;
    if (wid == NW - 1 && lane < FPS_CL) {        // reducer = highest wid (arbiter priority)
        r_slot0 = mapa32(pair0 + 8u * k, (uint32_t)lane);
        r_slot1 = mapa32(pair1 + 8u * k, (uint32_t)lane);
    }

    if (tid < 2 * FPS_CL)                        // init tags to 0xFF (never matches)
        ((unsigned long long*)s_key)[tid] = 0xFFFFFFFFFFFFFFFFull;
    if (tid == 0) s_hist[0] = 0;
    __syncthreads();
    asm volatile("barrier.cluster.arrive.aligned;" ::: "memory");
    asm volatile("barrier.cluster.wait.aligned;"   ::: "memory");

    float px = __ldg(&xb[0]);
    float py = __ldg(&xb[FPS_N]);
    float pz = __ldg(&xb[2 * FPS_N]);

    for (int it = 1; it < FPS_NP; it++) {
        const int u           = it - 1;
        const int buf         = u & 1;
        const uint32_t tag    = ((uint32_t)u >> 1) & 0xFFu;
        const uint32_t pbuf   = buf ? pair1 : pair0;
        const uint32_t r_slot = buf ? r_slot1 : r_slot0;

        uint64_t npx = pack2(-px, -px);
        uint64_t npy = pack2(-py, -py);
        uint64_t npz = pack2(-pz, -pz);

        // proven hot loop: packed distance + SEL-chain first-index argmax
        float bestd  = -1.0f;
        int   bestid = 0;
#pragma unroll
        for (int q = 0; q < NPAIR; q++) {
            uint64_t dx = add2(xp[q], npx);        // add(x,-p) bitwise == sub(x,p)
            uint64_t dy = add2(yp[q], npy);
            uint64_t dz = add2(zp[q], npz);
            // XLA order: (dx^2 + dy^2) + dz^2, separate .rn rounding
            uint64_t s = add2(add2(mul2(dx, dx), mul2(dy, dy)), mul2(dz, dz));
            float d0, d1; unpack2(s, d0, d1);
            const int p   = 2 * q;
            const int idx = pbase[q >> 1] + 2 * (q & 1);   // ascending within thread
            float n0 = fminf(dist[p], d0);     dist[p]     = n0;
            if (n0 > bestd) { bestd = n0; bestid = idx; }  // strict >: first idx wins
            float n1 = fminf(dist[p + 1], d1); dist[p + 1] = n1;
            if (n1 > bestd) { bestd = n1; bestid = idx + 1; }
        }

        // warp argmax: redux + ballot/ffs (lane order == index order)
        uint32_t db   = __float_as_uint(bestd);            // dists >= 0: u32 order == float
        uint32_t wmax = redux_max_u32(db);
        uint32_t msk  = __ballot_sync(0xFFFFFFFFu, db == wmax);
        if (lane == __ffs(msk) - 1)                        // lowest lane == smallest index
            s_wkey[wid] = ((uint64_t)wmax << 32) | (uint32_t)bestid;

        if (wid == NW - 1) {
            asm volatile("bar.sync 1, %0;" :: "r"(FPS_T) : "memory");
            uint64_t wkey = s_wkey[lane];                  // NW == 32; warp order == index order
            uint32_t d  = (uint32_t)(wkey >> 32);
            uint32_t wi = (uint32_t)wkey;
            uint32_t m    = redux_max_u32(d);
            uint32_t m2   = __ballot_sync(0xFFFFFFFFu, d == m);
            int ws        = __ffs(m2) - 1;                 // lowest warp == smallest index
            uint32_t widx0 = __shfl_sync(0xFFFFFFFFu, wi, ws);
            if (lane < FPS_CL) {
                uint64_t msg = ((uint64_t)m << 32) | (tag << 24) | widx0;
                st_cluster_u64(r_slot, msg);
            }
        } else {
            asm volatile("bar.arrive 1, %0;" :: "r"(FPS_T) : "memory");
        }

        // poll own slots; speculatively prefetch each slot's candidate coords
        uint32_t d = 0, ti = 0;
        float cx = 0.f, cy = 0.f, cz = 0.f;
        bool got = (lane >= FPS_CL);
        for (;;) {
            if (!got) {
                uint64_t v = lds_volatile_u64(pbuf + 8u * (uint32_t)lane);
                ti = (uint32_t)v;
                d  = (uint32_t)(v >> 32);
                if ((ti >> 24) == tag) {
                    got = true;
                    const int ci = (int)(ti & 0x00FFFFFFu);
                    cx = __ldcg(&xb[ci]);                  // issue now, consume later
                    cy = __ldcg(&xb[FPS_N + ci]);
                    cz = __ldcg(&xb[2 * FPS_N + ci]);
                }
            }
            if (__all_sync(0xFFFFFFFFu, got)) break;
        }

        // cluster argmax over 8 slots (slot order == index order)
        uint32_t dm = redux_max_u32(d);                    // lanes>=CL hold d=0
        uint32_t m3 = __ballot_sync(0xFFFFFFFFu, (lane < FPS_CL) && (d == dm));
        int rs      = __ffs(m3) - 1;

        // winner lane distributes pivot via smem (waits only ITS OWN prefetch)
        if (lane == rs) {
            s_piv[wid] = make_float4(cx, cy, cz, 0.f);     // STS.128
            if (wid == NW - 1) s_hist[it] = ti & 0x00FFFFFFu;
        }
        __syncwarp();
        float4 pv = s_piv[wid];                            // LDS.128 broadcast
        px = pv.x; py = pv.y; pz = pv.z;
    }

    // final gather: rank-0 CTA writes (3, 1024) for its batch
    __syncthreads();
    if (k == 0) {
        for (int i = tid; i < 3 * FPS_NP; i += FPS_T) {
            int ip = i & (FPS_NP - 1);
            int c  = i >> 10;
            uint32_t idx = s_hist[ip];
            out[((size_t)b * 3 + c) * FPS_NP + ip] = xb[(size_t)c * FPS_N + idx];
        }
    }
}

extern "C" void kernel_launch(void* const* d_in, const int* in_sizes, int n_in,
                              void* d_out, int out_size) {
    const float* pts = (const float*)d_in[0];
    float* out = (float*)d_out;
    fps_kernel<<<FPS_B * FPS_CL, FPS_T>>>(pts, out);
}

// round 14
// speedup vs baseline: 1.8856x; 1.8856x over previous
#include <cuda_runtime.h>
#include <cstdint>

// FPS: B=8, N=65536, select 1024. 8-CTA cluster per batch.
// Round-4 champion structure (996us): st.async+mbarrier key exchange,
// redux reduces, bar.arrive/sync split. Changes vs champion:
//  - reducer warp = highest wid (hi-wid-first arbiter priority)
//  - expect_tx repost + s_hist by reducer thread, after pivot LDG issue

#define FPS_B  8
#define FPS_N  65536
#define FPS_NP 1024
#define FPS_CL 8
#define FPS_T  1024
#define NW     (FPS_T / 32)
#define XBYTES (8u * FPS_CL)

__device__ __forceinline__ uint64_t pack2(float a, float b) {
    uint64_t r; asm("mov.b64 %0, {%1, %2};" : "=l"(r) : "f"(a), "f"(b)); return r;
}
__device__ __forceinline__ void unpack2(uint64_t v, float& a, float& b) {
    asm("mov.b64 {%0, %1}, %2;" : "=f"(a), "=f"(b) : "l"(v));
}
__device__ __forceinline__ uint64_t add2(uint64_t a, uint64_t b) {
    uint64_t r; asm("add.rn.f32x2 %0, %1, %2;" : "=l"(r) : "l"(a), "l"(b)); return r;
}
__device__ __forceinline__ uint64_t mul2(uint64_t a, uint64_t b) {
    uint64_t r; asm("mul.rn.f32x2 %0, %1, %2;" : "=l"(r) : "l"(a), "l"(b)); return r;
}
__device__ __forceinline__ uint32_t ctarank() {
    uint32_t r; asm("mov.u32 %0, %%cluster_ctarank;" : "=r"(r)); return r;
}
__device__ __forceinline__ uint32_t smem_u32(const void* p) {
    uint32_t a;
    asm("{ .reg .u64 t; cvta.to.shared.u64 t, %1; cvt.u32.u64 %0, t; }" : "=r"(a) : "l"(p));
    return a;
}
__device__ __forceinline__ uint32_t redux_max_u32(uint32_t v) {
    uint32_t r; asm("redux.sync.max.u32 %0, %1, 0xFFFFFFFF;" : "=r"(r) : "r"(v)); return r;
}
__device__ __forceinline__ uint32_t redux_min_u32(uint32_t v) {
    uint32_t r; asm("redux.sync.min.u32 %0, %1, 0xFFFFFFFF;" : "=r"(r) : "r"(v)); return r;
}
__device__ __forceinline__ void mbar_init(uint32_t mbar, uint32_t cnt) {
    asm volatile("mbarrier.init.shared.b64 [%0], %1;" :: "r"(mbar), "r"(cnt) : "memory");
}
__device__ __forceinline__ void mbar_expect_tx(uint32_t mbar, uint32_t bytes) {
    asm volatile("mbarrier.arrive.expect_tx.shared.b64 _, [%0], %1;"
                 :: "r"(mbar), "r"(bytes) : "memory");
}
__device__ __forceinline__ void mbar_wait(uint32_t mbar, uint32_t parity) {
    asm volatile(
        "{\n\t"
        ".reg .pred P;\n\t"
        "WL_%=:\n\t"
        "mbarrier.try_wait.parity.acquire.cluster.shared::cta.b64 P, [%0], %1, 0x989680;\n\t"
        "@P bra.uni WD_%=;\n\t"
        "bra.uni WL_%=;\n\t"
        "WD_%=:\n\t"
        "}"
        :: "r"(mbar), "r"(parity) : "memory");
}
__device__ __forceinline__ uint32_t mapa32(uint32_t laddr, uint32_t rank) {
    uint32_t r;
    asm("mapa.shared::cluster.u32 %0, %1, %2;" : "=r"(r) : "r"(laddr), "r"(rank));
    return r;
}
__device__ __forceinline__ void st_async_u64(uint32_t raddr, uint64_t v, uint32_t rmbar) {
    asm volatile("st.async.shared::cluster.mbarrier::complete_tx::bytes.b64 [%0], %1, [%2];"
                 :: "r"(raddr), "l"(v), "r"(rmbar) : "memory");
}
__device__ __forceinline__ void lds_v2(uint32_t addr, uint32_t& a, uint32_t& b) {
    asm volatile("ld.shared.v2.u32 {%0, %1}, [%2];" : "=r"(a), "=r"(b) : "r"(addr));
}

__global__ void __launch_bounds__(FPS_T, 1) __cluster_dims__(FPS_CL, 1, 1)
fps_kernel(const float* __restrict__ pts, float* __restrict__ out) {
    const int b      = blockIdx.x / FPS_CL;
    const uint32_t k = ctarank();
    const int tid    = threadIdx.x;
    const int lane   = tid & 31;
    const int wid    = tid >> 5;

    const float* __restrict__ xb = pts + (size_t)b * 3 * FPS_N;
    const float4* __restrict__ x4 = (const float4*)(xb);
    const float4* __restrict__ y4 = (const float4*)(xb + FPS_N);
    const float4* __restrict__ z4 = (const float4*)(xb + 2 * FPS_N);

    uint64_t xp[4], yp[4], zp[4];
    float dist[8];
    int pbase[2];

#pragma unroll
    for (int j = 0; j < 2; j++) {
        int f = (int)k * (FPS_N / 4 / FPS_CL) + tid + FPS_T * j;
        pbase[j] = 4 * f;
        float4 vx = x4[f], vy = y4[f], vz = z4[f];
        xp[2*j+0] = pack2(vx.x, vx.y);  xp[2*j+1] = pack2(vx.z, vx.w);
        yp[2*j+0] = pack2(vy.x, vy.y);  yp[2*j+1] = pack2(vy.z, vy.w);
        zp[2*j+0] = pack2(vz.x, vz.y);  zp[2*j+1] = pack2(vz.z, vz.w);
    }
#pragma unroll
    for (int p = 0; p < 8; p++) dist[p] = 1e10f;

    __shared__ uint32_t s_wd[NW], s_wi[NW];
    __shared__ alignas(16) uint64_t s_pair[2][FPS_CL];   // exchange: lo=d, hi=~idx
    __shared__ alignas(8)  uint64_t s_mbar[2];
    __shared__ uint32_t s_hist[FPS_NP];

    const uint32_t mb0 = smem_u32(&s_mbar[0]);
    const uint32_t mb1 = smem_u32(&s_mbar[1]);
    const uint32_t pair0 = smem_u32(&s_pair[0][0]);
    const uint32_t pair1 = smem_u32(&s_pair[1][0]);

    // reducer warp = highest wid (hi-wid-first arbiter priority)
    uint32_t r_slot0 = 0, r_slot1 = 0, r_mb0 = 0, r_mb1 = 0;
    if (wid == NW - 1 && lane < FPS_CL) {
        r_slot0 = mapa32(pair0 + 8u * k, (uint32_t)lane);
        r_slot1 = mapa32(pair1 + 8u * k, (uint32_t)lane);
        r_mb0   = mapa32(mb0, (uint32_t)lane);
        r_mb1   = mapa32(mb1, (uint32_t)lane);
    }

    if (tid == 0) {
        mbar_init(mb0, 1);
        mbar_init(mb1, 1);
        mbar_expect_tx(mb0, XBYTES);   // phase 0 of each buffer
        mbar_expect_tx(mb1, XBYTES);
        s_hist[0] = 0;
    }
    __syncthreads();
    asm volatile("barrier.cluster.arrive.aligned;" ::: "memory");
    asm volatile("barrier.cluster.wait.aligned;"   ::: "memory");

    float px = __ldg(&xb[0]);
    float py = __ldg(&xb[FPS_N]);
    float pz = __ldg(&xb[2 * FPS_N]);

    for (int it = 1; it < FPS_NP; it++) {
        const int u        = it - 1;
        const int buf      = u & 1;
        const uint32_t par = (u >> 1) & 1;
        const uint32_t mb     = buf ? mb1 : mb0;
        const uint32_t pbuf   = buf ? pair1 : pair0;
        const uint32_t r_slot = buf ? r_slot1 : r_slot0;
        const uint32_t r_mb   = buf ? r_mb1 : r_mb0;

        uint64_t npx = pack2(-px, -px);
        uint64_t npy = pack2(-py, -py);
        uint64_t npz = pack2(-pz, -pz);

        // champion hot loop: packed distance + SEL-chain first-index argmax
        float bestd  = -1.0f;
        int   bestid = 0;
#pragma unroll
        for (int q = 0; q < 4; q++) {
            uint64_t dx = add2(xp[q], npx);        // add(x,-p) bitwise == sub(x,p)
            uint64_t dy = add2(yp[q], npy);
            uint64_t dz = add2(zp[q], npz);
            // XLA order: (dx^2 + dy^2) + dz^2, separate .rn rounding
            uint64_t s = add2(add2(mul2(dx, dx), mul2(dy, dy)), mul2(dz, dz));
            float d0, d1; unpack2(s, d0, d1);
            const int p   = 2 * q;
            const int idx = pbase[q >> 1] + 2 * (q & 1);
            float n0 = fminf(dist[p], d0);     dist[p]     = n0;
            if (n0 > bestd) { bestd = n0; bestid = idx; }      // strict >: first idx wins
            float n1 = fminf(dist[p + 1], d1); dist[p + 1] = n1;
            if (n1 > bestd) { bestd = n1; bestid = idx + 1; }
        }

        // warp argmax (dists >= 0: u32 order == float order); first-index tie-break
        uint32_t db   = __float_as_uint(bestd);
        uint32_t wmax = redux_max_u32(db);
        uint32_t cand = (db == wmax) ? (uint32_t)bestid : 0xFFFFFFFFu;
        uint32_t wmin = redux_min_u32(cand);
        if (db == wmax && (uint32_t)bestid == wmin) {          // unique owner lane
            s_wd[wid] = wmax;
            s_wi[wid] = wmin;
        }

        if (wid == NW - 1) {
            asm volatile("bar.sync 1, %0;" :: "r"(FPS_T) : "memory");
            uint32_t d = s_wd[lane], i = s_wi[lane];           // NW == 32
            uint32_t m  = redux_max_u32(d);
            uint32_t c2 = (d == m) ? i : 0xFFFFFFFFu;
            uint32_t mi = redux_min_u32(c2);                   // smallest idx among tied
            if (lane < FPS_CL) {
                uint64_t msg = ((uint64_t)(~mi) << 32) | (uint64_t)m;  // lo=d, hi=~i
                st_async_u64(r_slot, msg, r_mb);
            }
        } else {
            asm volatile("bar.arrive 1, %0;" :: "r"(FPS_T) : "memory");
        }

        mbar_wait(mb, par);

        // per-warp reduce of CL exchanged candidates: 1 LDS.v2 + 2 redux
        uint32_t d = 0, ni = 0;
        if (lane < FPS_CL) lds_v2(pbuf + 8u * (uint32_t)lane, d, ni);
        uint32_t dm  = redux_max_u32(d);
        uint32_t nim = redux_max_u32((lane < FPS_CL && d == dm) ? ni : 0u);
        const int widx = (int)(~nim);

        // pivot fetch first (longest-latency op on the serial chain)
        px = __ldcg(&xb[widx]);
        py = __ldcg(&xb[FPS_N + widx]);
        pz = __ldcg(&xb[2 * FPS_N + widx]);

        // repost + history by reducer thread, off the LDG critical path.
        // Safe: repost(u) precedes this thread's send(u+1) in program order;
        // any peer's send(u+2) transitively requires our send(u+1).
        if (wid == NW - 1 && lane == 0) {
            s_hist[it] = (uint32_t)widx;
            mbar_expect_tx(mb, XBYTES);            // next phase of this buffer
        }
    }

    // final gather: rank-0 CTA writes (3, 1024) for its batch
    __syncthreads();
    if (k == 0) {
        for (int i = tid; i < 3 * FPS_NP; i += FPS_T) {
            int ip = i & (FPS_NP - 1);
            int c  = i >> 10;
            uint32_t idx = s_hist[ip];
            out[((size_t)b * 3 + c) * FPS_NP + ip] = xb[(size_t)c * FPS_N + idx];
        }
    }
}

extern "C" void kernel_launch(void* const* d_in, const int* in_sizes, int n_in,
                              void* d_out, int out_size) {
    const float* pts = (const float*)d_in[0];
    float* out = (float*)d_out;
    fps_kernel<<<FPS_B * FPS_CL, FPS_T>>>(pts, out);
}

// round 15
// speedup vs baseline: 1.8890x; 1.0019x over previous
#include <cuda_runtime.h>
#include <cstdint>

// FPS: B=8, N=65536, select 1024. 8-CTA cluster per batch.
// Champion (R14) structure + CTA-local points resident in dynamic smem:
// sender fetches winner coords via broadcast LDS.128 and ships them in the
// exchange message -> consumer pivot comes from local smem, no pivot LDG.

#define FPS_B  8
#define FPS_N  65536
#define FPS_NP 1024
#define FPS_CL 8
#define FPS_T  1024
#define NW     (FPS_T / 32)
#define PT_CTA (FPS_N / FPS_CL)          // 8192 points per CTA
#define SMEM_DYN (PT_CTA * 16)           // float4 per point = 131072 B
#define SLOT_B 32u                       // key@0, xy@16, zw@24
#define XBYTES (24u * FPS_CL)            // 3 u64 per peer

__device__ __forceinline__ uint64_t pack2(float a, float b) {
    uint64_t r; asm("mov.b64 %0, {%1, %2};" : "=l"(r) : "f"(a), "f"(b)); return r;
}
__device__ __forceinline__ void unpack2(uint64_t v, float& a, float& b) {
    asm("mov.b64 {%0, %1}, %2;" : "=f"(a), "=f"(b) : "l"(v));
}
__device__ __forceinline__ uint64_t add2(uint64_t a, uint64_t b) {
    uint64_t r; asm("add.rn.f32x2 %0, %1, %2;" : "=l"(r) : "l"(a), "l"(b)); return r;
}
__device__ __forceinline__ uint64_t mul2(uint64_t a, uint64_t b) {
    uint64_t r; asm("mul.rn.f32x2 %0, %1, %2;" : "=l"(r) : "l"(a), "l"(b)); return r;
}
__device__ __forceinline__ uint32_t ctarank() {
    uint32_t r; asm("mov.u32 %0, %%cluster_ctarank;" : "=r"(r)); return r;
}
__device__ __forceinline__ uint32_t smem_u32(const void* p) {
    uint32_t a;
    asm("{ .reg .u64 t; cvta.to.shared.u64 t, %1; cvt.u32.u64 %0, t; }" : "=r"(a) : "l"(p));
    return a;
}
__device__ __forceinline__ uint32_t redux_max_u32(uint32_t v) {
    uint32_t r; asm("redux.sync.max.u32 %0, %1, 0xFFFFFFFF;" : "=r"(r) : "r"(v)); return r;
}
__device__ __forceinline__ uint32_t redux_min_u32(uint32_t v) {
    uint32_t r; asm("redux.sync.min.u32 %0, %1, 0xFFFFFFFF;" : "=r"(r) : "r"(v)); return r;
}
__device__ __forceinline__ void mbar_init(uint32_t mbar, uint32_t cnt) {
    asm volatile("mbarrier.init.shared.b64 [%0], %1;" :: "r"(mbar), "r"(cnt) : "memory");
}
__device__ __forceinline__ void mbar_expect_tx(uint32_t mbar, uint32_t bytes) {
    asm volatile("mbarrier.arrive.expect_tx.shared.b64 _, [%0], %1;"
                 :: "r"(mbar), "r"(bytes) : "memory");
}
__device__ __forceinline__ void mbar_wait(uint32_t mbar, uint32_t parity) {
    asm volatile(
        "{\n\t"
        ".reg .pred P;\n\t"
        "WL_%=:\n\t"
        "mbarrier.try_wait.parity.acquire.cluster.shared::cta.b64 P, [%0], %1, 0x989680;\n\t"
        "@P bra.uni WD_%=;\n\t"
        "bra.uni WL_%=;\n\t"
        "WD_%=:\n\t"
        "}"
        :: "r"(mbar), "r"(parity) : "memory");
}
__device__ __forceinline__ uint32_t mapa32(uint32_t laddr, uint32_t rank) {
    uint32_t r;
    asm("mapa.shared::cluster.u32 %0, %1, %2;" : "=r"(r) : "r"(laddr), "r"(rank));
    return r;
}
__device__ __forceinline__ void st_async_u64(uint32_t raddr, uint64_t v, uint32_t rmbar) {
    asm volatile("st.async.shared::cluster.mbarrier::complete_tx::bytes.b64 [%0], %1, [%2];"
                 :: "r"(raddr), "l"(v), "r"(rmbar) : "memory");
}
__device__ __forceinline__ void lds_v2(uint32_t addr, uint32_t& a, uint32_t& b) {
    asm volatile("ld.shared.v2.u32 {%0, %1}, [%2];" : "=r"(a), "=r"(b) : "r"(addr));
}
__device__ __forceinline__ void lds_v2_u64(uint32_t addr, uint64_t& a, uint64_t& b) {
    asm volatile("ld.shared.v2.u64 {%0, %1}, [%2];" : "=l"(a), "=l"(b) : "r"(addr));
}

__global__ void __launch_bounds__(FPS_T, 1) __cluster_dims__(FPS_CL, 1, 1)
fps_kernel(const float* __restrict__ pts, float* __restrict__ out) {
    extern __shared__ float4 s_pts[];                 // this CTA's 8192 points

    const int b      = blockIdx.x / FPS_CL;
    const uint32_t k = ctarank();
    const int tid    = threadIdx.x;
    const int lane   = tid & 31;
    const int wid    = tid >> 5;

    const float* __restrict__ xb = pts + (size_t)b * 3 * FPS_N;
    const float4* __restrict__ x4 = (const float4*)(xb);
    const float4* __restrict__ y4 = (const float4*)(xb + FPS_N);
    const float4* __restrict__ z4 = (const float4*)(xb + 2 * FPS_N);

    uint64_t xp[4], yp[4], zp[4];
    float dist[8];
    int pbase[2];

#pragma unroll
    for (int j = 0; j < 2; j++) {
        int f = (int)k * (FPS_N / 4 / FPS_CL) + tid + FPS_T * j;   // global float4 idx
        pbase[j] = 4 * f;
        float4 vx = x4[f], vy = y4[f], vz = z4[f];
        xp[2*j+0] = pack2(vx.x, vx.y);  xp[2*j+1] = pack2(vx.z, vx.w);
        yp[2*j+0] = pack2(vy.x, vy.y);  yp[2*j+1] = pack2(vy.z, vy.w);
        zp[2*j+0] = pack2(vz.x, vz.y);  zp[2*j+1] = pack2(vz.z, vz.w);
        // stash this CTA's points in smem (local point id = 4*(tid + 1024*j) + e)
        int lp = 4 * (tid + FPS_T * j);
        s_pts[lp + 0] = make_float4(vx.x, vy.x, vz.x, 0.f);
        s_pts[lp + 1] = make_float4(vx.y, vy.y, vz.y, 0.f);
        s_pts[lp + 2] = make_float4(vx.z, vy.z, vz.z, 0.f);
        s_pts[lp + 3] = make_float4(vx.w, vy.w, vz.w, 0.f);
    }
#pragma unroll
    for (int p = 0; p < 8; p++) dist[p] = 1e10f;

    __shared__ uint32_t s_wd[NW], s_wi[NW];
    __shared__ alignas(16) unsigned char s_slot[2][FPS_CL * SLOT_B];
    __shared__ alignas(8)  uint64_t s_mbar[2];
    __shared__ uint32_t s_hist[FPS_NP];

    const uint32_t mb0 = smem_u32(&s_mbar[0]);
    const uint32_t mb1 = smem_u32(&s_mbar[1]);
    const uint32_t pair0 = smem_u32(&s_slot[0][0]);
    const uint32_t pair1 = smem_u32(&s_slot[1][0]);
    const uint32_t ptsa  = smem_u32(&s_pts[0]);

    // reducer warp = highest wid (hi-wid-first arbiter priority)
    uint32_t r_slot0 = 0, r_slot1 = 0, r_mb0 = 0, r_mb1 = 0;
    if (wid == NW - 1 && lane < FPS_CL) {
        r_slot0 = mapa32(pair0 + SLOT_B * k, (uint32_t)lane);
        r_slot1 = mapa32(pair1 + SLOT_B * k, (uint32_t)lane);
        r_mb0   = mapa32(mb0, (uint32_t)lane);
        r_mb1   = mapa32(mb1, (uint32_t)lane);
    }

    if (tid == 0) {
        mbar_init(mb0, 1);
        mbar_init(mb1, 1);
        mbar_expect_tx(mb0, XBYTES);   // phase 0 of each buffer
        mbar_expect_tx(mb1, XBYTES);
        s_hist[0] = 0;
    }
    __syncthreads();
    asm volatile("barrier.cluster.arrive.aligned;" ::: "memory");
    asm volatile("barrier.cluster.wait.aligned;"   ::: "memory");

    float px = __ldg(&xb[0]);
    float py = __ldg(&xb[FPS_N]);
    float pz = __ldg(&xb[2 * FPS_N]);

    for (int it = 1; it < FPS_NP; it++) {
        const int u        = it - 1;
        const int buf      = u & 1;
        const uint32_t par = (u >> 1) & 1;
        const uint32_t mb     = buf ? mb1 : mb0;
        const uint32_t pbuf   = buf ? pair1 : pair0;
        const uint32_t r_slot = buf ? r_slot1 : r_slot0;
        const uint32_t r_mb   = buf ? r_mb1 : r_mb0;

        uint64_t npx = pack2(-px, -px);
        uint64_t npy = pack2(-py, -py);
        uint64_t npz = pack2(-pz, -pz);

        // champion hot loop: packed distance + SEL-chain first-index argmax
        float bestd  = -1.0f;
        int   bestid = 0;
#pragma unroll
        for (int q = 0; q < 4; q++) {
            uint64_t dx = add2(xp[q], npx);        // add(x,-p) bitwise == sub(x,p)
            uint64_t dy = add2(yp[q], npy);
            uint64_t dz = add2(zp[q], npz);
            // XLA order: (dx^2 + dy^2) + dz^2, separate .rn rounding
            uint64_t s = add2(add2(mul2(dx, dx), mul2(dy, dy)), mul2(dz, dz));
            float d0, d1; unpack2(s, d0, d1);
            const int p   = 2 * q;
            const int idx = pbase[q >> 1] + 2 * (q & 1);
            float n0 = fminf(dist[p], d0);     dist[p]     = n0;
            if (n0 > bestd) { bestd = n0; bestid = idx; }      // strict >: first idx wins
            float n1 = fminf(dist[p + 1], d1); dist[p + 1] = n1;
            if (n1 > bestd) { bestd = n1; bestid = idx + 1; }
        }

        // warp argmax (dists >= 0: u32 order == float order); first-index tie-break
        uint32_t db   = __float_as_uint(bestd);
        uint32_t wmax = redux_max_u32(db);
        uint32_t cand = (db == wmax) ? (uint32_t)bestid : 0xFFFFFFFFu;
        uint32_t wmin = redux_min_u32(cand);
        if (db == wmax && (uint32_t)bestid == wmin) {          // unique owner lane
            s_wd[wid] = wmax;
            s_wi[wid] = wmin;
        }

        if (wid == NW - 1) {
            asm volatile("bar.sync 1, %0;" :: "r"(FPS_T) : "memory");
            uint32_t d = s_wd[lane], i = s_wi[lane];           // NW == 32
            uint32_t m  = redux_max_u32(d);
            uint32_t c2 = (d == m) ? i : 0xFFFFFFFFu;
            uint32_t mi = redux_min_u32(c2);                   // smallest idx among tied
            if (lane < FPS_CL) {
                // CTA winner is one of OUR points: coords from local smem (broadcast)
                uint32_t local = mi - ((uint32_t)k << 13);     // mi - k*8192
                uint64_t xy, zw;
                lds_v2_u64(ptsa + local * 16u, xy, zw);
                uint64_t key = ((uint64_t)(~mi) << 32) | (uint64_t)m;  // lo=d, hi=~i
                st_async_u64(r_slot,        key, r_mb);
                st_async_u64(r_slot + 16u,  xy,  r_mb);
                st_async_u64(r_slot + 24u,  zw,  r_mb);
            }
        } else {
            asm volatile("bar.arrive 1, %0;" :: "r"(FPS_T) : "memory");
        }

        mbar_wait(mb, par);

        // key reduce: 1 LDS.v2 + 2 redux (champion), + ballot/ffs for slot id
        uint32_t d = 0, ni = 0;
        if (lane < FPS_CL) lds_v2(pbuf + SLOT_B * (uint32_t)lane, d, ni);
        uint32_t dm  = redux_max_u32(d);
        uint32_t nim = redux_max_u32((lane < FPS_CL && d == dm) ? ni : 0u);
        uint32_t m3  = __ballot_sync(0xFFFFFFFFu,
                                     (lane < FPS_CL) && (d == dm) && (ni == nim));
        int rs       = __ffs(m3) - 1;
        const int widx = (int)(~nim);

        // pivot from exchanged coords (uniform broadcast LDS, no LDG)
        uint64_t wxy, wzz;
        lds_v2_u64(pbuf + SLOT_B * (uint32_t)rs + 16u, wxy, wzz);
        float zpad;
        unpack2(wxy, px, py);
        unpack2(wzz, pz, zpad);

        // repost + history by reducer thread (off critical path; same induction)
        if (wid == NW - 1 && lane == 0) {
            s_hist[it] = (uint32_t)widx;
            mbar_expect_tx(mb, XBYTES);            // next phase of this buffer
        }
    }

    // final gather: rank-0 CTA writes (3, 1024) for its batch
    __syncthreads();
    if (k == 0) {
        for (int i = tid; i < 3 * FPS_NP; i += FPS_T) {
            int ip = i & (FPS_NP - 1);
            int c  = i >> 10;
            uint32_t idx = s_hist[ip];
            out[((size_t)b * 3 + c) * FPS_NP + ip] = xb[(size_t)c * FPS_N + idx];
        }
    }
}

extern "C" void kernel_launch(void* const* d_in, const int* in_sizes, int n_in,
                              void* d_out, int out_size) {
    const float* pts = (const float*)d_in[0];
    float* out = (float*)d_out;

    cudaFuncSetAttribute(fps_kernel,
                         cudaFuncAttributeMaxDynamicSharedMemorySize, SMEM_DYN);
    fps_kernel<<<FPS_B * FPS_CL, FPS_T, SMEM_DYN>>>(pts, out);
}

// round 16
// speedup vs baseline: 2.1245x; 1.1246x over previous
#include <cuda_runtime.h>
#include <cstdint>

// FPS: B=8, N=65536, select 1024. 8-CTA cluster per batch.
// R15 champion + #pragma unroll 4 on the phase-period-4 main loop
// (folds buf/par/slot selects) + single STS.64 warp-winner write.

#define FPS_B  8
#define FPS_N  65536
#define FPS_NP 1024
#define FPS_CL 8
#define FPS_T  1024
#define NW     (FPS_T / 32)
#define PT_CTA (FPS_N / FPS_CL)          // 8192 points per CTA
#define SMEM_DYN (PT_CTA * 16)           // float4 per point = 131072 B
#define SLOT_B 32u                       // key@0, xy@16, zw@24
#define XBYTES (24u * FPS_CL)            // 3 u64 per peer

__device__ __forceinline__ uint64_t pack2(float a, float b) {
    uint64_t r; asm("mov.b64 %0, {%1, %2};" : "=l"(r) : "f"(a), "f"(b)); return r;
}
__device__ __forceinline__ void unpack2(uint64_t v, float& a, float& b) {
    asm("mov.b64 {%0, %1}, %2;" : "=f"(a), "=f"(b) : "l"(v));
}
__device__ __forceinline__ uint64_t add2(uint64_t a, uint64_t b) {
    uint64_t r; asm("add.rn.f32x2 %0, %1, %2;" : "=l"(r) : "l"(a), "l"(b)); return r;
}
__device__ __forceinline__ uint64_t mul2(uint64_t a, uint64_t b) {
    uint64_t r; asm("mul.rn.f32x2 %0, %1, %2;" : "=l"(r) : "l"(a), "l"(b)); return r;
}
__device__ __forceinline__ uint32_t ctarank() {
    uint32_t r; asm("mov.u32 %0, %%cluster_ctarank;" : "=r"(r)); return r;
}
__device__ __forceinline__ uint32_t smem_u32(const void* p) {
    uint32_t a;
    asm("{ .reg .u64 t; cvta.to.shared.u64 t, %1; cvt.u32.u64 %0, t; }" : "=r"(a) : "l"(p));
    return a;
}
__device__ __forceinline__ uint32_t redux_max_u32(uint32_t v) {
    uint32_t r; asm("redux.sync.max.u32 %0, %1, 0xFFFFFFFF;" : "=r"(r) : "r"(v)); return r;
}
__device__ __forceinline__ uint32_t redux_min_u32(uint32_t v) {
    uint32_t r; asm("redux.sync.min.u32 %0, %1, 0xFFFFFFFF;" : "=r"(r) : "r"(v)); return r;
}
__device__ __forceinline__ void mbar_init(uint32_t mbar, uint32_t cnt) {
    asm volatile("mbarrier.init.shared.b64 [%0], %1;" :: "r"(mbar), "r"(cnt) : "memory");
}
__device__ __forceinline__ void mbar_expect_tx(uint32_t mbar, uint32_t bytes) {
    asm volatile("mbarrier.arrive.expect_tx.shared.b64 _, [%0], %1;"
                 :: "r"(mbar), "r"(bytes) : "memory");
}
__device__ __forceinline__ void mbar_wait(uint32_t mbar, uint32_t parity) {
    asm volatile(
        "{\n\t"
        ".reg .pred P;\n\t"
        "WL_%=:\n\t"
        "mbarrier.try_wait.parity.acquire.cluster.shared::cta.b64 P, [%0], %1, 0x989680;\n\t"
        "@P bra.uni WD_%=;\n\t"
        "bra.uni WL_%=;\n\t"
        "WD_%=:\n\t"
        "}"
        :: "r"(mbar), "r"(parity) : "memory");
}
__device__ __forceinline__ uint32_t mapa32(uint32_t laddr, uint32_t rank) {
    uint32_t r;
    asm("mapa.shared::cluster.u32 %0, %1, %2;" : "=r"(r) : "r"(laddr), "r"(rank));
    return r;
}
__device__ __forceinline__ void st_async_u64(uint32_t raddr, uint64_t v, uint32_t rmbar) {
    asm volatile("st.async.shared::cluster.mbarrier::complete_tx::bytes.b64 [%0], %1, [%2];"
                 :: "r"(raddr), "l"(v), "r"(rmbar) : "memory");
}
__device__ __forceinline__ void lds_v2(uint32_t addr, uint32_t& a, uint32_t& b) {
    asm volatile("ld.shared.v2.u32 {%0, %1}, [%2];" : "=r"(a), "=r"(b) : "r"(addr));
}
__device__ __forceinline__ void lds_v2_u64(uint32_t addr, uint64_t& a, uint64_t& b) {
    asm volatile("ld.shared.v2.u64 {%0, %1}, [%2];" : "=l"(a), "=l"(b) : "r"(addr));
}

__global__ void __launch_bounds__(FPS_T, 1) __cluster_dims__(FPS_CL, 1, 1)
fps_kernel(const float* __restrict__ pts, float* __restrict__ out) {
    extern __shared__ float4 s_pts[];                 // this CTA's 8192 points

    const int b      = blockIdx.x / FPS_CL;
    const uint32_t k = ctarank();
    const int tid    = threadIdx.x;
    const int lane   = tid & 31;
    const int wid    = tid >> 5;

    const float* __restrict__ xb = pts + (size_t)b * 3 * FPS_N;
    const float4* __restrict__ x4 = (const float4*)(xb);
    const float4* __restrict__ y4 = (const float4*)(xb + FPS_N);
    const float4* __restrict__ z4 = (const float4*)(xb + 2 * FPS_N);

    uint64_t xp[4], yp[4], zp[4];
    float dist[8];
    int pbase[2];

#pragma unroll
    for (int j = 0; j < 2; j++) {
        int f = (int)k * (FPS_N / 4 / FPS_CL) + tid + FPS_T * j;   // global float4 idx
        pbase[j] = 4 * f;
        float4 vx = x4[f], vy = y4[f], vz = z4[f];
        xp[2*j+0] = pack2(vx.x, vx.y);  xp[2*j+1] = pack2(vx.z, vx.w);
        yp[2*j+0] = pack2(vy.x, vy.y);  yp[2*j+1] = pack2(vy.z, vy.w);
        zp[2*j+0] = pack2(vz.x, vz.y);  zp[2*j+1] = pack2(vz.z, vz.w);
        int lp = 4 * (tid + FPS_T * j);
        s_pts[lp + 0] = make_float4(vx.x, vy.x, vz.x, 0.f);
        s_pts[lp + 1] = make_float4(vx.y, vy.y, vz.y, 0.f);
        s_pts[lp + 2] = make_float4(vx.z, vy.z, vz.z, 0.f);
        s_pts[lp + 3] = make_float4(vx.w, vy.w, vz.w, 0.f);
    }
#pragma unroll
    for (int p = 0; p < 8; p++) dist[p] = 1e10f;

    __shared__ uint64_t s_wkey[NW];                   // (d<<32)|idx per warp
    __shared__ alignas(16) unsigned char s_slot[2][FPS_CL * SLOT_B];
    __shared__ alignas(8)  uint64_t s_mbar[2];
    __shared__ uint32_t s_hist[FPS_NP];

    const uint32_t mb0 = smem_u32(&s_mbar[0]);
    const uint32_t mb1 = smem_u32(&s_mbar[1]);
    const uint32_t pair0 = smem_u32(&s_slot[0][0]);
    const uint32_t pair1 = smem_u32(&s_slot[1][0]);
    const uint32_t ptsa  = smem_u32(&s_pts[0]);

    // reducer warp = highest wid (hi-wid-first arbiter priority)
    uint32_t r_slot0 = 0, r_slot1 = 0, r_mb0 = 0, r_mb1 = 0;
    if (wid == NW - 1 && lane < FPS_CL) {
        r_slot0 = mapa32(pair0 + SLOT_B * k, (uint32_t)lane);
        r_slot1 = mapa32(pair1 + SLOT_B * k, (uint32_t)lane);
        r_mb0   = mapa32(mb0, (uint32_t)lane);
        r_mb1   = mapa32(mb1, (uint32_t)lane);
    }

    if (tid == 0) {
        mbar_init(mb0, 1);
        mbar_init(mb1, 1);
        mbar_expect_tx(mb0, XBYTES);   // phase 0 of each buffer
        mbar_expect_tx(mb1, XBYTES);
        s_hist[0] = 0;
    }
    __syncthreads();
    asm volatile("barrier.cluster.arrive.aligned;" ::: "memory");
    asm volatile("barrier.cluster.wait.aligned;"   ::: "memory");

    float px = __ldg(&xb[0]);
    float py = __ldg(&xb[FPS_N]);
    float pz = __ldg(&xb[2 * FPS_N]);

#pragma unroll 4
    for (int it = 1; it < FPS_NP; it++) {
        const int u        = it - 1;
        const int buf      = u & 1;                    // folds per unrolled copy
        const uint32_t par = ((uint32_t)u >> 1) & 1;
        const uint32_t mb     = buf ? mb1 : mb0;
        const uint32_t pbuf   = buf ? pair1 : pair0;
        const uint32_t r_slot = buf ? r_slot1 : r_slot0;
        const uint32_t r_mb   = buf ? r_mb1 : r_mb0;

        uint64_t npx = pack2(-px, -px);
        uint64_t npy = pack2(-py, -py);
        uint64_t npz = pack2(-pz, -pz);

        // champion hot loop: packed distance + SEL-chain first-index argmax
        float bestd  = -1.0f;
        int   bestid = 0;
#pragma unroll
        for (int q = 0; q < 4; q++) {
            uint64_t dx = add2(xp[q], npx);        // add(x,-p) bitwise == sub(x,p)
            uint64_t dy = add2(yp[q], npy);
            uint64_t dz = add2(zp[q], npz);
            // XLA order: (dx^2 + dy^2) + dz^2, separate .rn rounding
            uint64_t s = add2(add2(mul2(dx, dx), mul2(dy, dy)), mul2(dz, dz));
            float d0, d1; unpack2(s, d0, d1);
            const int p   = 2 * q;
            const int idx = pbase[q >> 1] + 2 * (q & 1);
            float n0 = fminf(dist[p], d0);     dist[p]     = n0;
            if (n0 > bestd) { bestd = n0; bestid = idx; }      // strict >: first idx wins
            float n1 = fminf(dist[p + 1], d1); dist[p + 1] = n1;
            if (n1 > bestd) { bestd = n1; bestid = idx + 1; }
        }

        // warp argmax (dists >= 0: u32 order == float order); first-index tie-break
        uint32_t db   = __float_as_uint(bestd);
        uint32_t wmax = redux_max_u32(db);
        uint32_t cand = (db == wmax) ? (uint32_t)bestid : 0xFFFFFFFFu;
        uint32_t wmin = redux_min_u32(cand);
        if (db == wmax && (uint32_t)bestid == wmin)            // unique owner lane
            s_wkey[wid] = ((uint64_t)wmax << 32) | (uint64_t)wmin;   // one STS.64

        if (wid == NW - 1) {
            asm volatile("bar.sync 1, %0;" :: "r"(FPS_T) : "memory");
            uint64_t wkey = s_wkey[lane];                      // NW == 32
            uint32_t d = (uint32_t)(wkey >> 32);
            uint32_t i = (uint32_t)wkey;
            uint32_t m  = redux_max_u32(d);
            uint32_t c2 = (d == m) ? i : 0xFFFFFFFFu;
            uint32_t mi = redux_min_u32(c2);                   // smallest idx among tied
            if (lane < FPS_CL) {
                // CTA winner is one of OUR points: coords from local smem (broadcast)
                uint32_t local = mi - ((uint32_t)k << 13);     // mi - k*8192
                uint64_t xy, zw;
                lds_v2_u64(ptsa + local * 16u, xy, zw);
                uint64_t key = ((uint64_t)(~mi) << 32) | (uint64_t)m;  // lo=d, hi=~i
                st_async_u64(r_slot,        key, r_mb);
                st_async_u64(r_slot + 16u,  xy,  r_mb);
                st_async_u64(r_slot + 24u,  zw,  r_mb);
            }
        } else {
            asm volatile("bar.arrive 1, %0;" :: "r"(FPS_T) : "memory");
        }

        mbar_wait(mb, par);

        // key reduce: 1 LDS.v2 + 2 redux + ballot/ffs for winning slot
        uint32_t d = 0, ni = 0;
        if (lane < FPS_CL) lds_v2(pbuf + SLOT_B * (uint32_t)lane, d, ni);
        uint32_t dm  = redux_max_u32(d);
        uint32_t nim = redux_max_u32((lane < FPS_CL && d == dm) ? ni : 0u);
        uint32_t m3  = __ballot_sync(0xFFFFFFFFu,
                                     (lane < FPS_CL) && (d == dm) && (ni == nim));
        int rs       = __ffs(m3) - 1;
        const int widx = (int)(~nim);

        // pivot from exchanged coords (uniform broadcast LDS, no LDG)
        uint64_t wxy, wzz;
        lds_v2_u64(pbuf + SLOT_B * (uint32_t)rs + 16u, wxy, wzz);
        float zpad;
        unpack2(wxy, px, py);
        unpack2(wzz, pz, zpad);

        // repost + history by reducer thread (off critical path; same induction)
        if (wid == NW - 1 && lane == 0) {
            s_hist[it] = (uint32_t)widx;
            mbar_expect_tx(mb, XBYTES);            // next phase of this buffer
        }
    }

    // final gather: rank-0 CTA writes (3, 1024) for its batch
    __syncthreads();
    if (k == 0) {
        for (int i = tid; i < 3 * FPS_NP; i += FPS_T) {
            int ip = i & (FPS_NP - 1);
            int c  = i >> 10;
            uint32_t idx = s_hist[ip];
            out[((size_t)b * 3 + c) * FPS_NP + ip] = xb[(size_t)c * FPS_N + idx];
        }
    }
}

extern "C" void kernel_launch(void* const* d_in, const int* in_sizes, int n_in,
                              void* d_out, int out_size) {
    const float* pts = (const float*)d_in[0];
    float* out = (float*)d_out;

    cudaFuncSetAttribute(fps_kernel,
                         cudaFuncAttributeMaxDynamicSharedMemorySize, SMEM_DYN);
    fps_kernel<<<FPS_B * FPS_CL, FPS_T, SMEM_DYN>>>(pts, out);
}